// round 14
// baseline (speedup 1.0000x reference)
#include <cuda_runtime.h>

// Problem constants
#define T_LEN   4096
#define D_DIM   512
#define N_DIM   16
#define TWO_N   32
#define DQ      128            // D/4 (float4 groups per row)
#define SEG     128            // number of segments
#define L_SEG   32             // steps per segment (SEG*L_SEG == T_LEN)
#define CG      2048           // chain groups = N*D/4
#define HN      8              // heads per half
#define HCG     1024           // chain groups per half

// Scratch (device globals). Layout: [CG][SEG] float4.
__device__ float4 g_b  [CG*SEG];
__device__ float4 g_sq [CG*SEG];
__device__ float4 g_sd [CG*SEG];
__device__ float4 g_hab[CG*SEG];
__device__ float4 g_hvb[CG*SEG];

__device__ __forceinline__ float sqrt_approx(float v) {
    float r;
    asm("sqrt.approx.f32 %0, %1;" : "=f"(r) : "f"(v));
    return r;
}

// ---------------------------------------------------------------------------
// K1 (half): zero-state replay -> b, Sq, Sd for heads [n0, n0+8).
// 2 float4 n-chains (8 scalar chains) per thread (R9 shape).
// Threads: SEG * 4 * DQ = 65536 -> 256 blocks.
// ---------------------------------------------------------------------------
__global__ void k_b(const float4* __restrict__ x4, const float4* __restrict__ a4p,
                    int n0) {
    int tid = blockIdx.x * blockDim.x + threadIdx.x;
    int s   = tid >> 9;            // segment 0..127
    int r   = tid & 511;
    int np  = r >> 7;              // n-pair 0..3
    int g   = r & (DQ - 1);

    float a[8], om[8], q[8], Sq[8], Sd[8];
    #pragma unroll
    for (int j = 0; j < 2; j++) {
        float4 av = a4p[(n0 + np * 2 + j) * DQ + g];
        a[j*4+0] = av.x; a[j*4+1] = av.y; a[j*4+2] = av.z; a[j*4+3] = av.w;
    }
    #pragma unroll
    for (int k = 0; k < 8; k++) { om[k] = 1.f - a[k]; q[k] = 0.f; Sq[k] = 0.f; Sd[k] = 0.f; }

    const float4* xp = x4 + (size_t)(s * L_SEG) * DQ + g;

    #pragma unroll 4
    for (int i = 0; i < L_SEG; i++) {
        float4 xv = xp[(size_t)i * DQ];
        float xs[4] = {xv.x, xv.y, xv.z, xv.w};
        #pragma unroll
        for (int j = 0; j < 2; j++) {
            #pragma unroll
            for (int cc = 0; cc < 4; cc++) {
                int k = j * 4 + cc;
                float d = xs[cc] - q[k];
                Sq[k] = fmaf(om[k], Sq[k], d * d);
                Sd[k] = Sd[k] + d;
                q[k]  = fmaf(a[k], d, q[k]);
            }
        }
    }
    #pragma unroll
    for (int j = 0; j < 2; j++) {
        int cg = (n0 + np * 2 + j) * DQ + g;
        g_b [cg * SEG + s] = make_float4(q [j*4+0], q [j*4+1], q [j*4+2], q [j*4+3]);
        g_sq[cg * SEG + s] = make_float4(Sq[j*4+0], Sq[j*4+1], Sq[j*4+2], Sq[j*4+3]);
        g_sd[cg * SEG + s] = make_float4(Sd[j*4+0], Sd[j*4+1], Sd[j*4+2], Sd[j*4+3]);
    }
}

// ---------------------------------------------------------------------------
// K2 (half): combined warp scan for chain groups [n0*DQ, n0*DQ + 1024).
// 4 segments per lane; writes boundaries and FINAL states (lane 31).
// Threads: 1024 warps = 32768 -> 128 blocks.
// ---------------------------------------------------------------------------
__global__ void k_scan2(const float4* __restrict__ ha0,
                        const float4* __restrict__ hs0,
                        const float4* __restrict__ a4p,
                        float4* __restrict__ out4,
                        int n0) {
    int cg   = n0 * DQ + ((blockIdx.x * blockDim.x + threadIdx.x) >> 5);
    int lane = threadIdx.x & 31;

    float4 av = a4p[cg];
    float al[4] = {av.x, av.y, av.z, av.w};
    float om[4], P[4];
    #pragma unroll
    for (int j = 0; j < 4; j++) { om[j] = 1.f - al[j]; P[j] = om[j]; }
    #pragma unroll
    for (int k = 0; k < 5; k++) {
        #pragma unroll
        for (int j = 0; j < 4; j++) P[j] *= P[j];   // (1-a)^32
    }

    float b[4][4], sq[4][4], sd[4][4];
    #pragma unroll
    for (int m = 0; m < 4; m++) {
        float4 bv  = g_b [cg * SEG + 4 * lane + m];
        float4 sqv = g_sq[cg * SEG + 4 * lane + m];
        float4 sdv = g_sd[cg * SEG + 4 * lane + m];
        b [m][0] = bv.x;  b [m][1] = bv.y;  b [m][2] = bv.z;  b [m][3] = bv.w;
        sq[m][0] = sqv.x; sq[m][1] = sqv.y; sq[m][2] = sqv.z; sq[m][3] = sqv.w;
        sd[m][0] = sdv.x; sd[m][1] = sdv.y; sd[m][2] = sdv.z; sd[m][3] = sdv.w;
    }

    // ---------- scan 1: ha ----------
    float A[4], Q[4], pw[4], qs[5][4];
    #pragma unroll
    for (int j = 0; j < 4; j++) {
        float t = fmaf(P[j], b[0][j], b[1][j]);
        t = fmaf(P[j], t, b[2][j]);
        A[j] = fmaf(P[j], t, b[3][j]);
        float p2 = P[j] * P[j];
        Q[j]  = p2 * p2;
        pw[j] = Q[j];
    }
    #pragma unroll
    for (int step = 0; step < 5; step++) {
        int off = 1 << step;
        float t[4];
        #pragma unroll
        for (int j = 0; j < 4; j++) {
            qs[step][j] = pw[j];
            t[j] = __shfl_up_sync(0xFFFFFFFFu, A[j], off);
        }
        if (lane >= off) {
            #pragma unroll
            for (int j = 0; j < 4; j++) A[j] = fmaf(pw[j], t[j], A[j]);
        }
        #pragma unroll
        for (int j = 0; j < 4; j++) pw[j] *= pw[j];
    }
    float Ql[4] = {1.f, 1.f, 1.f, 1.f};
    #pragma unroll
    for (int bit = 0; bit < 5; bit++) {
        if (lane & (1 << bit)) {
            #pragma unroll
            for (int j = 0; j < 4; j++) Ql[j] *= qs[bit][j];
        }
    }
    float excl[4];
    #pragma unroll
    for (int j = 0; j < 4; j++) {
        excl[j] = __shfl_up_sync(0xFFFFFFFFu, A[j], 1);
        if (lane == 0) excl[j] = 0.f;
    }
    float4 h0v = ha0[cg];
    float h0[4] = {h0v.x, h0v.y, h0v.z, h0v.w};
    float Ha[4][4];
    #pragma unroll
    for (int j = 0; j < 4; j++) {
        Ha[0][j] = fmaf(Ql[j], h0[j], excl[j]);
        Ha[1][j] = fmaf(P[j], Ha[0][j], b[0][j]);
        Ha[2][j] = fmaf(P[j], Ha[1][j], b[1][j]);
        Ha[3][j] = fmaf(P[j], Ha[2][j], b[2][j]);
    }
    #pragma unroll
    for (int m = 0; m < 4; m++)
        g_hab[cg * SEG + 4 * lane + m] =
            make_float4(Ha[m][0], Ha[m][1], Ha[m][2], Ha[m][3]);

    // ---------- build hv forcing ----------
    float f[4][4];
    #pragma unroll
    for (int j = 0; j < 4; j++) {
        float aom = al[j] * om[j];
        float apf = al[j] * P[j];
        float p1p = P[j] * (1.f - P[j]);
        #pragma unroll
        for (int m = 0; m < 4; m++) {
            float H = Ha[m][j];
            f[m][j] = aom * sq[m][j] - 2.f * H * apf * sd[m][j] + H * H * p1p;
        }
    }

    // ---------- scan 2: hv ----------
    float B[4];
    #pragma unroll
    for (int j = 0; j < 4; j++) {
        float t = fmaf(P[j], f[0][j], f[1][j]);
        t = fmaf(P[j], t, f[2][j]);
        B[j] = fmaf(P[j], t, f[3][j]);
    }
    #pragma unroll
    for (int step = 0; step < 5; step++) {
        int off = 1 << step;
        float t[4];
        #pragma unroll
        for (int j = 0; j < 4; j++) t[j] = __shfl_up_sync(0xFFFFFFFFu, B[j], off);
        if (lane >= off) {
            #pragma unroll
            for (int j = 0; j < 4; j++) B[j] = fmaf(qs[step][j], t[j], B[j]);
        }
    }
    float excl2[4];
    #pragma unroll
    for (int j = 0; j < 4; j++) {
        excl2[j] = __shfl_up_sync(0xFFFFFFFFu, B[j], 1);
        if (lane == 0) excl2[j] = 0.f;
    }
    float4 hsv = hs0[cg];
    float v0[4] = {hsv.x * hsv.x, hsv.y * hsv.y, hsv.z * hsv.z, hsv.w * hsv.w};
    float Hv[4][4];
    #pragma unroll
    for (int j = 0; j < 4; j++) {
        Hv[0][j] = fmaxf(fmaf(Ql[j], v0[j], excl2[j]), 0.f);
        Hv[1][j] = fmaxf(fmaf(P[j], Hv[0][j], f[0][j]), 0.f);
        Hv[2][j] = fmaxf(fmaf(P[j], Hv[1][j], f[1][j]), 0.f);
        Hv[3][j] = fmaxf(fmaf(P[j], Hv[2][j], f[2][j]), 0.f);
    }
    #pragma unroll
    for (int m = 0; m < 4; m++)
        g_hvb[cg * SEG + 4 * lane + m] =
            make_float4(Hv[m][0], Hv[m][1], Hv[m][2], Hv[m][3]);

    // ---------- final states (lane 31 holds the last segment) ----------
    if (lane == 31) {
        const size_t base = (size_t)T_LEN * TWO_N * DQ;   // float4 units
        float haN[4], hvN[4];
        #pragma unroll
        for (int j = 0; j < 4; j++) {
            haN[j] = fmaf(P[j], Ha[3][j], b[3][j]);
            hvN[j] = fmaxf(fmaf(P[j], Hv[3][j], f[3][j]), 0.f);
        }
        out4[base + cg] = make_float4(haN[0], haN[1], haN[2], haN[3]);
        out4[base + CG + cg] =
            make_float4(sqrt_approx(hvN[0]), sqrt_approx(hvN[1]),
                        sqrt_approx(hvN[2]), sqrt_approx(hvN[3]));
    }
}

// ---------------------------------------------------------------------------
// K3 (half): fused writer for heads [n0, n0+8).  R9 per-thread shape
// (1 cg, 32 steps).  Threads: SEG * 1024 = 131072 -> 512 blocks.
// ---------------------------------------------------------------------------
__global__ void k_out(const float4* __restrict__ x4, const float4* __restrict__ a4p,
                      float4* __restrict__ out4, int n0) {
    int tid = blockIdx.x * blockDim.x + threadIdx.x;
    int s  = tid >> 10;            // segment 0..127
    int cl = tid & (HCG - 1);
    int n  = n0 + (cl >> 7);
    int g  = cl & (DQ - 1);
    int cg = n * DQ + g;

    float4 a = a4p[cg];
    float omx = 1.f - a.x, omy = 1.f - a.y, omz = 1.f - a.z, omw = 1.f - a.w;

    float4 ha = g_hab[cg * SEG + s];
    float4 hv = g_hvb[cg * SEG + s];
    int t0 = s * L_SEG;

    #pragma unroll 4
    for (int i = 0; i < L_SEG; i++) {
        int t = t0 + i;
        float4 xv = x4[(size_t)t * DQ + g];
        float ux = xv.x - ha.x, uy = xv.y - ha.y, uz = xv.z - ha.z, uw = xv.w - ha.w;
        hv.x = omx * fmaf(a.x, ux * ux, hv.x);
        hv.y = omy * fmaf(a.y, uy * uy, hv.y);
        hv.z = omz * fmaf(a.z, uz * uz, hv.z);
        hv.w = omw * fmaf(a.w, uw * uw, hv.w);
        ha.x = fmaf(a.x, ux, ha.x);
        ha.y = fmaf(a.y, uy, ha.y);
        ha.z = fmaf(a.z, uz, ha.z);
        ha.w = fmaf(a.w, uw, ha.w);
        size_t row = (size_t)t * TWO_N;
        __stcs(&out4[(row + n) * DQ + g], ha);
        __stcs(&out4[(row + N_DIM + n) * DQ + g],
               make_float4(sqrt_approx(hv.x), sqrt_approx(hv.y),
                           sqrt_approx(hv.z), sqrt_approx(hv.w)));
    }
}

// ---------------------------------------------------------------------------
// Half-pipeline overlap: half-B's issue-bound compute (b+scan) runs on a
// non-blocking stream concurrently with half-A's DRAM-bound writer.
// ---------------------------------------------------------------------------
extern "C" void kernel_launch(void* const* d_in, const int* in_sizes, int n_in,
                              void* d_out, int out_size) {
    const float4* x4  = (const float4*)d_in[0];   // [T, D]
    const float4* ha0 = (const float4*)d_in[1];   // [N, D]
    const float4* hs0 = (const float4*)d_in[2];   // [N, D]
    const float4* a4  = (const float4*)d_in[3];   // [N, D]
    float4* out4 = (float4*)d_out;

    static cudaStream_t s2 = nullptr;
    static cudaEvent_t evA = nullptr, evB = nullptr;
    if (!s2) {
        cudaStreamCreateWithFlags(&s2, cudaStreamNonBlocking);
        cudaEventCreateWithFlags(&evA, cudaEventDisableTiming);
        cudaEventCreateWithFlags(&evB, cudaEventDisableTiming);
    }

    // Half A: compute then writer on main stream
    k_b    <<<256, 256>>>(x4, a4, 0);
    k_scan2<<<128, 256>>>(ha0, hs0, a4, out4, 0);
    cudaEventRecord(evA, 0);
    k_out  <<<512, 256>>>(x4, a4, out4, 0);      // DRAM-bound, ~21 us

    // Half B: compute on s2, overlapping out_A
    cudaStreamWaitEvent(s2, evA, 0);
    k_b    <<<256, 256, 0, s2>>>(x4, a4, HN);
    k_scan2<<<128, 256, 0, s2>>>(ha0, hs0, a4, out4, HN);
    cudaEventRecord(evB, s2);

    // Half B writer on main stream (after out_A and scan_B)
    cudaStreamWaitEvent(0, evB, 0);
    k_out  <<<512, 256>>>(x4, a4, out4, HN);
}

// round 15
// speedup vs baseline: 1.1978x; 1.1978x over previous
#include <cuda_runtime.h>

// Problem constants
#define T_LEN   4096
#define D_DIM   512
#define N_DIM   16
#define TWO_N   32
#define DQ      128            // D/4 (float4 groups per row)
#define SEG     128            // number of segments
#define L_SEG   32             // steps per segment (SEG*L_SEG == T_LEN)
#define CG      2048           // chain groups = N*D/4
#define BIG_THREADS (SEG*CG)   // 262144

// Scratch (device globals). Layout: [CG][SEG] float4.
// NOTE: Sd eliminated — Sd = b/a exactly (telescoping), folded into the
// hv forcing as -2*H*P*b.
__device__ float4 g_b  [CG*SEG];
__device__ float4 g_sq [CG*SEG];
__device__ float4 g_hab[CG*SEG];
__device__ float4 g_hvb[CG*SEG];

__device__ __forceinline__ float sqrt_approx(float v) {
    float r;
    asm("sqrt.approx.f32 %0, %1;" : "=f"(r) : "f"(v));
    return r;
}

// ---------------------------------------------------------------------------
// K1: zero-state replay per segment -> b, Sq.   (R9 shape, 4 ops/chain-step)
// 2 float4 n-chains (8 scalar chains) per thread, shared x load:
// threads = SEG * 8 * DQ = 131072; 32 steps each.
// ---------------------------------------------------------------------------
__global__ void k_b(const float4* __restrict__ x4, const float4* __restrict__ a4p) {
    int tid = blockIdx.x * blockDim.x + threadIdx.x;
    int s   = tid >> 10;           // segment 0..127
    int r   = tid & 1023;
    int np  = r >> 7;              // n-pair 0..7 (covers n = np*2, np*2+1)
    int g   = r & (DQ - 1);

    float a[8], om[8], q[8], Sq[8];
    #pragma unroll
    for (int j = 0; j < 2; j++) {
        float4 av = a4p[(np * 2 + j) * DQ + g];
        a[j*4+0] = av.x; a[j*4+1] = av.y; a[j*4+2] = av.z; a[j*4+3] = av.w;
    }
    #pragma unroll
    for (int k = 0; k < 8; k++) { om[k] = 1.f - a[k]; q[k] = 0.f; Sq[k] = 0.f; }

    const float4* xp = x4 + (size_t)(s * L_SEG) * DQ + g;

    #pragma unroll 4
    for (int i = 0; i < L_SEG; i++) {
        float4 xv = xp[(size_t)i * DQ];
        float xs[4] = {xv.x, xv.y, xv.z, xv.w};
        #pragma unroll
        for (int j = 0; j < 2; j++) {
            #pragma unroll
            for (int cc = 0; cc < 4; cc++) {
                int k = j * 4 + cc;
                float d = xs[cc] - q[k];
                Sq[k] = fmaf(om[k], Sq[k], d * d);
                q[k]  = fmaf(a[k], d, q[k]);
            }
        }
    }
    #pragma unroll
    for (int j = 0; j < 2; j++) {
        int cg = (np * 2 + j) * DQ + g;
        g_b [cg * SEG + s] = make_float4(q [j*4+0], q [j*4+1], q [j*4+2], q [j*4+3]);
        g_sq[cg * SEG + s] = make_float4(Sq[j*4+0], Sq[j*4+1], Sq[j*4+2], Sq[j*4+3]);
    }
}

// ---------------------------------------------------------------------------
// K2: combined warp scan over 128 segments, 4 segments per lane.  (R9 config)
// hv forcing uses the Sd-free form:
//   f = a*om*Sq - 2*H*P*b + H^2*P*(1-P)
// ---------------------------------------------------------------------------
__global__ void k_scan2(const float4* __restrict__ ha0,
                        const float4* __restrict__ hs0,
                        const float4* __restrict__ a4p) {
    int cg   = (blockIdx.x * blockDim.x + threadIdx.x) >> 5;
    int lane = threadIdx.x & 31;

    float4 av = a4p[cg];
    float al[4] = {av.x, av.y, av.z, av.w};
    float om[4], P[4];
    #pragma unroll
    for (int j = 0; j < 4; j++) { om[j] = 1.f - al[j]; P[j] = om[j]; }
    #pragma unroll
    for (int k = 0; k < 5; k++) {
        #pragma unroll
        for (int j = 0; j < 4; j++) P[j] *= P[j];   // (1-a)^32
    }

    float b[4][4], sq[4][4];
    #pragma unroll
    for (int m = 0; m < 4; m++) {
        float4 bv  = g_b [cg * SEG + 4 * lane + m];
        float4 sqv = g_sq[cg * SEG + 4 * lane + m];
        b [m][0] = bv.x;  b [m][1] = bv.y;  b [m][2] = bv.z;  b [m][3] = bv.w;
        sq[m][0] = sqv.x; sq[m][1] = sqv.y; sq[m][2] = sqv.z; sq[m][3] = sqv.w;
    }

    // ---------- scan 1: ha ----------
    float A[4], Q[4], pw[4], qs[5][4];
    #pragma unroll
    for (int j = 0; j < 4; j++) {
        float t = fmaf(P[j], b[0][j], b[1][j]);
        t = fmaf(P[j], t, b[2][j]);
        A[j] = fmaf(P[j], t, b[3][j]);
        float p2 = P[j] * P[j];
        Q[j]  = p2 * p2;
        pw[j] = Q[j];
    }
    #pragma unroll
    for (int step = 0; step < 5; step++) {
        int off = 1 << step;
        float t[4];
        #pragma unroll
        for (int j = 0; j < 4; j++) {
            qs[step][j] = pw[j];
            t[j] = __shfl_up_sync(0xFFFFFFFFu, A[j], off);
        }
        if (lane >= off) {
            #pragma unroll
            for (int j = 0; j < 4; j++) A[j] = fmaf(pw[j], t[j], A[j]);
        }
        #pragma unroll
        for (int j = 0; j < 4; j++) pw[j] *= pw[j];
    }
    float Ql[4] = {1.f, 1.f, 1.f, 1.f};
    #pragma unroll
    for (int bit = 0; bit < 5; bit++) {
        if (lane & (1 << bit)) {
            #pragma unroll
            for (int j = 0; j < 4; j++) Ql[j] *= qs[bit][j];
        }
    }
    float excl[4];
    #pragma unroll
    for (int j = 0; j < 4; j++) {
        excl[j] = __shfl_up_sync(0xFFFFFFFFu, A[j], 1);
        if (lane == 0) excl[j] = 0.f;
    }
    float4 h0v = ha0[cg];
    float h0[4] = {h0v.x, h0v.y, h0v.z, h0v.w};
    float Ha[4][4];
    #pragma unroll
    for (int j = 0; j < 4; j++) {
        Ha[0][j] = fmaf(Ql[j], h0[j], excl[j]);
        Ha[1][j] = fmaf(P[j], Ha[0][j], b[0][j]);
        Ha[2][j] = fmaf(P[j], Ha[1][j], b[1][j]);
        Ha[3][j] = fmaf(P[j], Ha[2][j], b[2][j]);
    }
    #pragma unroll
    for (int m = 0; m < 4; m++)
        g_hab[cg * SEG + 4 * lane + m] =
            make_float4(Ha[m][0], Ha[m][1], Ha[m][2], Ha[m][3]);

    // ---------- build hv forcing (Sd-free) ----------
    float f[4][4];
    #pragma unroll
    for (int j = 0; j < 4; j++) {
        float aom = al[j] * om[j];
        float p1p = P[j] * (1.f - P[j]);
        #pragma unroll
        for (int m = 0; m < 4; m++) {
            float H = Ha[m][j];
            f[m][j] = aom * sq[m][j] - 2.f * H * P[j] * b[m][j] + H * H * p1p;
        }
    }

    // ---------- scan 2: hv ----------
    float B[4];
    #pragma unroll
    for (int j = 0; j < 4; j++) {
        float t = fmaf(P[j], f[0][j], f[1][j]);
        t = fmaf(P[j], t, f[2][j]);
        B[j] = fmaf(P[j], t, f[3][j]);
    }
    #pragma unroll
    for (int step = 0; step < 5; step++) {
        int off = 1 << step;
        float t[4];
        #pragma unroll
        for (int j = 0; j < 4; j++) t[j] = __shfl_up_sync(0xFFFFFFFFu, B[j], off);
        if (lane >= off) {
            #pragma unroll
            for (int j = 0; j < 4; j++) B[j] = fmaf(qs[step][j], t[j], B[j]);
        }
    }
    float excl2[4];
    #pragma unroll
    for (int j = 0; j < 4; j++) {
        excl2[j] = __shfl_up_sync(0xFFFFFFFFu, B[j], 1);
        if (lane == 0) excl2[j] = 0.f;
    }
    float4 hsv = hs0[cg];
    float v0[4] = {hsv.x * hsv.x, hsv.y * hsv.y, hsv.z * hsv.z, hsv.w * hsv.w};
    float Hv[4][4];
    #pragma unroll
    for (int j = 0; j < 4; j++) {
        Hv[0][j] = fmaxf(fmaf(Ql[j], v0[j], excl2[j]), 0.f);
        Hv[1][j] = fmaxf(fmaf(P[j], Hv[0][j], f[0][j]), 0.f);
        Hv[2][j] = fmaxf(fmaf(P[j], Hv[1][j], f[1][j]), 0.f);
        Hv[3][j] = fmaxf(fmaf(P[j], Hv[2][j], f[2][j]), 0.f);
    }
    #pragma unroll
    for (int m = 0; m < 4; m++)
        g_hvb[cg * SEG + 4 * lane + m] =
            make_float4(Hv[m][0], Hv[m][1], Hv[m][2], Hv[m][3]);
}

// ---------------------------------------------------------------------------
// K3: fused writer (R9 config: 1 cg/thread, 262144 threads).
// ---------------------------------------------------------------------------
__global__ void k_out(const float4* __restrict__ x4, const float4* __restrict__ a4p,
                      float4* __restrict__ out4) {
    int tid = blockIdx.x * blockDim.x + threadIdx.x;
    int s  = tid >> 11;          // segment 0..127
    int cg = tid & (CG - 1);
    int n  = cg >> 7;
    int g  = cg & (DQ - 1);

    float4 a = a4p[cg];
    float omx = 1.f - a.x, omy = 1.f - a.y, omz = 1.f - a.z, omw = 1.f - a.w;

    float4 ha = g_hab[cg * SEG + s];
    float4 hv = g_hvb[cg * SEG + s];
    int t0 = s * L_SEG;

    #pragma unroll 4
    for (int i = 0; i < L_SEG; i++) {
        int t = t0 + i;
        float4 xv = x4[(size_t)t * DQ + g];
        float ux = xv.x - ha.x, uy = xv.y - ha.y, uz = xv.z - ha.z, uw = xv.w - ha.w;
        hv.x = omx * fmaf(a.x, ux * ux, hv.x);
        hv.y = omy * fmaf(a.y, uy * uy, hv.y);
        hv.z = omz * fmaf(a.z, uz * uz, hv.z);
        hv.w = omw * fmaf(a.w, uw * uw, hv.w);
        ha.x = fmaf(a.x, ux, ha.x);
        ha.y = fmaf(a.y, uy, ha.y);
        ha.z = fmaf(a.z, uz, ha.z);
        ha.w = fmaf(a.w, uw, ha.w);
        size_t row = (size_t)t * TWO_N;
        __stcs(&out4[(row + n) * DQ + g], ha);
        __stcs(&out4[(row + N_DIM + n) * DQ + g],
               make_float4(sqrt_approx(hv.x), sqrt_approx(hv.y),
                           sqrt_approx(hv.z), sqrt_approx(hv.w)));
    }

    if (s == SEG - 1) {
        const size_t base = (size_t)T_LEN * TWO_N * DQ;   // float4 units
        out4[base + cg] = ha;
        out4[base + CG + cg] =
            make_float4(sqrt_approx(hv.x), sqrt_approx(hv.y),
                        sqrt_approx(hv.z), sqrt_approx(hv.w));
    }
}

// ---------------------------------------------------------------------------
extern "C" void kernel_launch(void* const* d_in, const int* in_sizes, int n_in,
                              void* d_out, int out_size) {
    const float4* x4  = (const float4*)d_in[0];   // [T, D]
    const float4* ha0 = (const float4*)d_in[1];   // [N, D]
    const float4* hs0 = (const float4*)d_in[2];   // [N, D]
    const float4* a4  = (const float4*)d_in[3];   // [N, D]
    float4* out4 = (float4*)d_out;

    k_b    <<<(SEG * 8 * DQ) / 256, 256>>>(x4, a4);
    k_scan2<<<(CG * 32) / 256, 256>>>(ha0, hs0, a4);
    k_out  <<<BIG_THREADS / 256, 256>>>(x4, a4, out4);
}